// round 3
// baseline (speedup 1.0000x reference)
#include <cuda_runtime.h>

// GINConv, N=2048, F=32, E=16, K=32, adj density ~5%.
// Output layout: [adj (N*N)] [out (N*K)] [edges (N*N*E)]  -- flattened tuple.
//
// Strategy: the problem is a 272MB pass-through copy + tiny sparse GNN math.
// One block per row i fuses: adj-row copy + nonzero compaction, edges-slice
// copy (warms cache for the gather), sparse relu-message accumulation, and
// the 32x32 epilogue GEMVs. A small precompute kernel produces
// node_part = nodes @ W_ne[:F] and node_term = relu(nodes @ W_n + b_n).

#define Nn 2048
#define Ff 32
#define Ee 16
#define Kk 32

#define OFF_OUT   ((size_t)Nn * Nn)
#define OFF_EDGES ((size_t)Nn * Nn + (size_t)Nn * Kk)

__device__ float g_node_part[Nn * Ff];
__device__ float g_node_term[Nn * Ff];

// -------- kernel 1: per-node precompute (warp per row, lane = feature) -----
__global__ void __launch_bounds__(256) node_pre_kernel(
    const float* __restrict__ nodes, const float* __restrict__ W_ne,
    const float* __restrict__ W_n, const float* __restrict__ b_n)
{
    __shared__ float W1[Ff * Ff];   // W_ne[:F]  (node part of concat weight)
    __shared__ float W2[Ff * Ff];   // W_n
    int tid = threadIdx.x;
    for (int t = tid; t < Ff * Ff; t += 256) {
        W1[t] = W_ne[t];        // W_ne is [F+E, F] row-major; first F rows
        W2[t] = W_n[t];
    }
    __syncthreads();

    int warp = tid >> 5, lane = tid & 31;
    int j = blockIdx.x * 8 + warp;
    if (j < Nn) {
        float x = nodes[j * Ff + lane];
        float p = 0.f, t = 0.f;
#pragma unroll
        for (int g = 0; g < Ff; g++) {
            float nv = __shfl_sync(0xffffffffu, x, g);
            p = fmaf(nv, W1[g * Ff + lane], p);
            t = fmaf(nv, W2[g * Ff + lane], t);
        }
        g_node_part[j * Ff + lane] = p;                 // bias b_ne added later
        g_node_term[j * Ff + lane] = fmaxf(t + b_n[lane], 0.f);
    }
}

// -------- kernel 2: fused copy + sparse message + epilogue (block per row) --
__global__ void __launch_bounds__(256) gin_main_kernel(
    const float* __restrict__ adj, const float* __restrict__ edges,
    const float* __restrict__ W_ne, const float* __restrict__ b_ne,
    const float* __restrict__ W_net, const float* __restrict__ b_net,
    const float* __restrict__ eps, float* __restrict__ out)
{
    __shared__ float We_s[Ee * Ff];          // 2 KB  (W_ne rows F..F+E)
    __shared__ float Wnet_s[Ff * Kk];        // 4 KB
    __shared__ float bne_s[Ff], bnet_s[Kk];
    __shared__ unsigned short nbr[Nn];       // 4 KB compacted neighbor ids
    __shared__ int cnt;
    __shared__ float red[8 * Ff];            // per-warp partial messages
    __shared__ float pre_s[Ff];

    const int tid = threadIdx.x;
    const int i = blockIdx.x;

    for (int t = tid; t < Ee * Ff; t += 256) We_s[t] = W_ne[Ff * Ff + t];
    for (int t = tid; t < Ff * Kk; t += 256) Wnet_s[t] = W_net[t];
    if (tid < Ff) bne_s[tid] = b_ne[tid];
    if (tid < Kk) bnet_s[tid] = b_net[tid];
    if (tid == 0) cnt = 0;
    __syncthreads();

    // ---- adj row: copy to output + compact nonzeros (order-free, sum only) ----
    const float4* adj4  = (const float4*)(adj + (size_t)i * Nn);
    float4*       oadj4 = (float4*)(out + (size_t)i * Nn);
#pragma unroll
    for (int it = 0; it < 2; it++) {
        int idx = tid + it * 256;            // 0..511 float4s = 2048 floats
        float4 a = adj4[idx];
        oadj4[idx] = a;
        int jb = idx * 4;
        if (a.x != 0.f) { int p = atomicAdd(&cnt, 1); nbr[p] = (unsigned short)(jb + 0); }
        if (a.y != 0.f) { int p = atomicAdd(&cnt, 1); nbr[p] = (unsigned short)(jb + 1); }
        if (a.z != 0.f) { int p = atomicAdd(&cnt, 1); nbr[p] = (unsigned short)(jb + 2); }
        if (a.w != 0.f) { int p = atomicAdd(&cnt, 1); nbr[p] = (unsigned short)(jb + 3); }
    }

    // ---- edges slice: straight copy (128 KB/row); also warms cache ----
    const float4* e4  = (const float4*)(edges + (size_t)i * Nn * Ee);
    float4*       oe4 = (float4*)(out + OFF_EDGES + (size_t)i * Nn * Ee);
#pragma unroll 8
    for (int idx = tid; idx < (Nn * Ee) / 4; idx += 256)
        oe4[idx] = e4[idx];

    __syncthreads();

    // ---- sparse message: warp per neighbor, lane = output feature f ----
    const int nnbr = cnt;
    const int warp = tid >> 5, lane = tid & 31;
    const float* erow = edges + (size_t)i * Nn * Ee;
    const float* arow = adj + (size_t)i * Nn;
    float acc = 0.f;
    for (int n = warp; n < nnbr; n += 8) {
        int j = nbr[n];
        // lanes 0..15 each hold one of the 16 edge features; broadcast via shfl
        float ev = erow[j * Ee + (lane & (Ee - 1))];
        float part = 0.f;
#pragma unroll
        for (int e = 0; e < Ee; e++) {
            float v = __shfl_sync(0xffffffffu, ev, e);
            part = fmaf(v, We_s[e * Ff + lane], part);
        }
        float val = fmaxf(part + g_node_part[j * Ff + lane] + bne_s[lane], 0.f);
        acc = fmaf(val, arow[j], acc);       // weight by adj value (it is 1.0)
    }
    red[warp * Ff + lane] = acc;
    __syncthreads();

    // ---- epilogue: warp 0 reduces, applies eps, and does the 32x32 GEMV ----
    if (warp == 0) {
        float msg = 0.f;
#pragma unroll
        for (int w = 0; w < 8; w++) msg += red[w * Ff + lane];
        float p = (1.f + eps[0]) * g_node_term[(size_t)i * Ff + lane] + msg;
        pre_s[lane] = p;
        __syncwarp();
        float o = bnet_s[lane];
#pragma unroll
        for (int f = 0; f < Ff; f++)
            o = fmaf(pre_s[f], Wnet_s[f * Kk + lane], o);
        out[OFF_OUT + (size_t)i * Kk + lane] = fmaxf(o, 0.f);
    }
}

extern "C" void kernel_launch(void* const* d_in, const int* in_sizes, int n_in,
                              void* d_out, int out_size)
{
    const float* adj    = (const float*)d_in[0];
    const float* nodes  = (const float*)d_in[1];
    const float* edges  = (const float*)d_in[2];
    const float* W_ne   = (const float*)d_in[3];
    const float* b_ne   = (const float*)d_in[4];
    const float* W_n    = (const float*)d_in[5];
    const float* b_n    = (const float*)d_in[6];
    const float* W_net  = (const float*)d_in[7];
    const float* b_net  = (const float*)d_in[8];
    const float* eps    = (const float*)d_in[9];
    float* out = (float*)d_out;

    node_pre_kernel<<<Nn / 8, 256>>>(nodes, W_ne, W_n, b_n);
    gin_main_kernel<<<Nn, 256>>>(adj, edges, W_ne, b_ne, W_net, b_net, eps, out);
}

// round 10
// speedup vs baseline: 1.0269x; 1.0269x over previous
#include <cuda_runtime.h>

// GINConv N=2048, F=32, E=16, K=32, adj density ~5%.
// Output tuple layout: [adj N*N][out N*K][edges N*N*E], all fp32.
//
// One fused kernel, one block per graph row i:
//   1) stage the tiny weight matrices in smem
//   2) adj row: streaming copy out + ballot-compacted neighbor list
//   3) sparse message: for each neighbor j, recompute node_part[j] and
//      edge_part via shfl-broadcast GEMVs against smem weights; relu; sum.
//      (adj nonzeros are exactly 1.0f -> no weight multiply needed)
//   4) edges row slice: 128 KB streaming copy (ILP-4, evict-first)
//   5) epilogue: (1+eps)*relu(x_i W_n + b_n) + msg, then 32x32 GEMV + relu

#define NN 2048
#define FF 32
#define EE 16
#define KK 32

#define OUT_OFF   ((size_t)NN * NN)
#define EDGE_OFF  ((size_t)NN * NN + (size_t)NN * KK)

__global__ void __launch_bounds__(256) ginconv_fused(
    const float* __restrict__ adj,   const float* __restrict__ nodes,
    const float* __restrict__ edges,
    const float* __restrict__ W_ne,  const float* __restrict__ b_ne,
    const float* __restrict__ W_n,   const float* __restrict__ b_n,
    const float* __restrict__ W_net, const float* __restrict__ b_net,
    const float* __restrict__ eps,   float* __restrict__ out)
{
    __shared__ float sW1[FF * FF];        // W_ne rows 0..F-1  (node slice)
    __shared__ float sWe[EE * FF];        // W_ne rows F..F+E-1 (edge slice)
    __shared__ float sW2[FF * FF];        // W_n
    __shared__ float sW3[FF * KK];        // W_net
    __shared__ float sbne[FF];
    __shared__ float spart[8 * FF];       // per-warp message partials
    __shared__ float spre[FF];
    __shared__ unsigned short snbr[NN];
    __shared__ int scnt;

    const int tid  = threadIdx.x;
    const int row  = blockIdx.x;
    const int wrp  = tid >> 5;
    const int lane = tid & 31;

    // 1) weight staging (W_ne is [(F+E), F] row-major, contiguous W1 then We)
    for (int t = tid; t < (FF + EE) * FF; t += 256) {
        float v = W_ne[t];
        if (t < FF * FF) sW1[t] = v;
        else             sWe[t - FF * FF] = v;
    }
    for (int t = tid; t < FF * FF; t += 256) sW2[t] = W_n[t];
    for (int t = tid; t < FF * KK; t += 256) sW3[t] = W_net[t];
    if (tid < FF) sbne[tid] = b_ne[tid];
    if (tid == 0) scnt = 0;
    __syncthreads();

    // 2) adj row: streaming copy + warp-ballot compaction (sum is order-free)
    {
        const float4* src = (const float4*)(adj + (size_t)row * NN);
        float4*       dst = (float4*)(out + (size_t)row * NN);
        const unsigned ltmask = (1u << lane) - 1u;
#pragma unroll
        for (int it = 0; it < 2; ++it) {
            int idx = tid + it * 256;           // 512 float4 = 2048 floats
            float4 a = __ldcs(src + idx);
            __stcs(dst + idx, a);
            unsigned m0 = __ballot_sync(0xffffffffu, a.x != 0.f);
            unsigned m1 = __ballot_sync(0xffffffffu, a.y != 0.f);
            unsigned m2 = __ballot_sync(0xffffffffu, a.z != 0.f);
            unsigned m3 = __ballot_sync(0xffffffffu, a.w != 0.f);
            int tot = __popc(m0) + __popc(m1) + __popc(m2) + __popc(m3);
            int base = 0;
            if (lane == 0 && tot) base = atomicAdd(&scnt, tot);
            base = __shfl_sync(0xffffffffu, base, 0);
            int jb = idx * 4;
            if (a.x != 0.f) snbr[base + __popc(m0 & ltmask)] = (unsigned short)(jb);
            base += __popc(m0);
            if (a.y != 0.f) snbr[base + __popc(m1 & ltmask)] = (unsigned short)(jb + 1);
            base += __popc(m1);
            if (a.z != 0.f) snbr[base + __popc(m2 & ltmask)] = (unsigned short)(jb + 2);
            base += __popc(m2);
            if (a.w != 0.f) snbr[base + __popc(m3 & ltmask)] = (unsigned short)(jb + 3);
        }
    }
    __syncthreads();

    // 3) sparse message BEFORE the bulk copy (cold lines read once; the copy
    //    afterwards hits them in L2). Warp per neighbor, lane = out feature.
    {
        const int nnz = scnt;
        const float* erow = edges + (size_t)row * NN * EE;
        float acc = 0.f;
        for (int n = wrp; n < nnz; n += 8) {
            int j = snbr[n];
            float xg = nodes[j * FF + lane];               // node feature g=lane
            float ev = erow[j * EE + (lane & (EE - 1))];   // edge feats on lanes 0..15
            float s = sbne[lane];
#pragma unroll
            for (int g = 0; g < FF; ++g)
                s = fmaf(__shfl_sync(0xffffffffu, xg, g), sW1[g * FF + lane], s);
#pragma unroll
            for (int e = 0; e < EE; ++e)
                s = fmaf(__shfl_sync(0xffffffffu, ev, e), sWe[e * FF + lane], s);
            acc += fmaxf(s, 0.f);                          // adj value == 1.0f
        }
        spart[wrp * FF + lane] = acc;
    }

    // 4) edges slice: 128 KB streaming copy, 4-deep register batching
    {
        const float4* src = (const float4*)(edges + (size_t)row * NN * EE) + tid;
        float4*       dst = (float4*)(out + EDGE_OFF + (size_t)row * NN * EE) + tid;
#pragma unroll
        for (int it = 0; it < 8; ++it) {
            float4 r0 = __ldcs(src);
            float4 r1 = __ldcs(src + 256);
            float4 r2 = __ldcs(src + 512);
            float4 r3 = __ldcs(src + 768);
            __stcs(dst,       r0);
            __stcs(dst + 256, r1);
            __stcs(dst + 512, r2);
            __stcs(dst + 768, r3);
            src += 1024;
            dst += 1024;
        }
    }
    __syncthreads();

    // 5) epilogue on warp 0: reduce partials, node term, eps, final GEMV+relu
    if (wrp == 0) {
        float msg = 0.f;
#pragma unroll
        for (int w = 0; w < 8; ++w) msg += spart[w * FF + lane];
        float xi = nodes[(size_t)row * FF + lane];
        float t = b_n[lane];
#pragma unroll
        for (int g = 0; g < FF; ++g)
            t = fmaf(__shfl_sync(0xffffffffu, xi, g), sW2[g * FF + lane], t);
        spre[lane] = (1.f + eps[0]) * fmaxf(t, 0.f) + msg;
        __syncwarp();
        float o = b_net[lane];
#pragma unroll
        for (int f = 0; f < FF; ++f)
            o = fmaf(spre[f], sW3[f * KK + lane], o);
        out[OUT_OFF + (size_t)row * KK + lane] = fmaxf(o, 0.f);
    }
}

extern "C" void kernel_launch(void* const* d_in, const int* in_sizes, int n_in,
                              void* d_out, int out_size)
{
    const float* adj   = (const float*)d_in[0];
    const float* nodes = (const float*)d_in[1];
    const float* edges = (const float*)d_in[2];
    const float* W_ne  = (const float*)d_in[3];
    const float* b_ne  = (const float*)d_in[4];
    const float* W_n   = (const float*)d_in[5];
    const float* b_n   = (const float*)d_in[6];
    const float* W_net = (const float*)d_in[7];
    const float* b_net = (const float*)d_in[8];
    const float* eps   = (const float*)d_in[9];

    ginconv_fused<<<NN, 256>>>(adj, nodes, edges, W_ne, b_ne, W_n, b_n,
                               W_net, b_net, eps, (float*)d_out);
}